// round 13
// baseline (speedup 1.0000x reference)
#include <cuda_runtime.h>
#include <math.h>

#define BB 32
#define LQd 64
#define Ed 512
#define NFd 10
#define FLd 40
#define Dd 512
#define Hd 512
#define Ad 512
#define Rd 1024
#define Vd 50257

#define MQ (BB*LQd)        // 2048 rows
#define MF (BB*NFd*FLd)    // 12800 rows
#define QBLKS (MQ/64)      // 32
#define FBLKS (MF/64)      // 200

// output offsets (flattened tuple: logits, h, c, q_vec, q_logits)
#define OFF_H     (BB*Vd)
#define OFF_C     (OFF_H + BB*Hd)
#define OFF_QVEC  (OFF_C + BB*Hd)
#define OFF_QLOG  (OFF_QVEC + BB*Ed)

// score-kernel dynamic smem layout (floats)
#define AS_STRIDE 36        // 144B rows: 16B-aligned, conflict-free
#define BS_STRIDE 136       // 544B rows: 16B-aligned, conflict-free
#define AS_FLOATS (2*64*AS_STRIDE)
#define BS_FLOATS (2*32*BS_STRIDE)
#define SCORE_SMEM_BYTES ((AS_FLOATS + BS_FLOATS + 64)*4)

// -------- scratch (device globals; no allocation allowed) --------
__device__ float g_qscore[MQ];
__device__ float g_fscore[MF];
__device__ float g_qdec[BB*Ad];
__device__ float g_fdec[BB*Ad];
__device__ float g_x[BB*1536];     // [prev_emb | f_vec | q_vec]
__device__ float g_z[BB*2048];
__device__ float g_r[BB*Rd];
__device__ float g_h[BB*Hd];
__device__ float g_qw[MQ];         // question softmax weights
__device__ int   g_tidx[BB*40];    // facts top-k indices (unordered)
__device__ float g_tw[BB*40];      // facts top-k softmax weights

// -------- helpers --------
__device__ __forceinline__ float to_tf32(float x) {
    unsigned u;
    asm("cvt.rna.tf32.f32 %0, %1;" : "=r"(u) : "f"(x));
    return __uint_as_float(u);
}
__device__ __forceinline__ unsigned fu(float x) { return __float_as_uint(x); }

__device__ __forceinline__ void mma_tf32(float c[4],
    unsigned a0, unsigned a1, unsigned a2, unsigned a3,
    unsigned b0, unsigned b1) {
    asm volatile(
        "mma.sync.aligned.m16n8k8.row.col.f32.tf32.tf32.f32 "
        "{%0,%1,%2,%3},{%4,%5,%6,%7},{%8,%9},{%0,%1,%2,%3};\n"
        : "+f"(c[0]), "+f"(c[1]), "+f"(c[2]), "+f"(c[3])
        : "r"(a0), "r"(a1), "r"(a2), "r"(a3), "r"(b0), "r"(b1));
}

__device__ __forceinline__ void cp16(void* s, const void* g) {
    unsigned sa = (unsigned)__cvta_generic_to_shared(s);
    asm volatile("cp.async.ca.shared.global [%0], [%1], 16;\n" :: "r"(sa), "l"(g));
}
__device__ __forceinline__ void cp_commit() {
    asm volatile("cp.async.commit_group;\n");
}
template<int N> __device__ __forceinline__ void cp_wait() {
    asm volatile("cp.async.wait_group %0;\n" :: "n"(N));
}

// -------- prep: zero accumulators, seed biases, copy prev_emb --------
__global__ void prep_kernel(const float* __restrict__ prev_emb,
                            const float* __restrict__ lstm_bias,
                            const float* __restrict__ br,
                            const float* __restrict__ bu,
                            const float* __restrict__ bv) {
    int i = blockIdx.x * 256 + threadIdx.x;   // grid covers 65536
    if (i < MQ)      g_qscore[i] = 0.f;
    if (i < MF)      g_fscore[i] = 0.f;
    if (i < BB*Ad)   { g_qdec[i] = 0.f; g_fdec[i] = 0.f; }
    if (i < BB*Ed)   { int b = i >> 9, e = i & 511; g_x[b*1536 + e] = prev_emb[i]; }
    if (i < BB*2048) g_z[i] = lstm_bias[i & 2047];
    if (i < BB*Rd)   { int u = i & 1023; g_r[i] = br[u] + bu[u] + bv[u]; }
}

// -------- tf32 MMA 32-row GEMM accumulator body --------
// Z[32,N] += X[32, kbase..kbase+kchunk) @ W[kbase..,c0..c0+128)  (atomicAdd)
__device__ __forceinline__ void mma32_body(
    const float* __restrict__ X, int lda, const float* __restrict__ W,
    int N, int kbase, int kchunk, float* __restrict__ Z, int c0) {
    __shared__ float As[32][36];
    __shared__ float Bs[32][132];
    const int t = threadIdx.x;
    const int lane = t & 31;
    const int w = t >> 5;
    const int wr = w & 1;          // 2 row groups of 16
    const int wc = w >> 1;         // 4 col groups of 32
    const int gid = lane >> 2;
    const int qid = lane & 3;

    float c[4][4];
#pragma unroll
    for (int j = 0; j < 4; j++)
#pragma unroll
        for (int i = 0; i < 4; i++) c[j][i] = 0.f;

    for (int k0 = kbase; k0 < kbase + kchunk; k0 += 32) {
        {   // X tile 32x32
            int r = t >> 3, cg = (t & 7) * 4;
            float4 v0 = *(const float4*)(X + (size_t)r*lda + k0 + cg);
            As[r][cg+0] = to_tf32(v0.x); As[r][cg+1] = to_tf32(v0.y);
            As[r][cg+2] = to_tf32(v0.z); As[r][cg+3] = to_tf32(v0.w);
        }
        {   // W tile 32x128
            int rr = t >> 3, cc = (t & 7) * 16;
            const float* src = W + (size_t)(k0 + rr)*N + c0 + cc;
#pragma unroll
            for (int q = 0; q < 4; q++) {
                float4 wv = *(const float4*)(src + q*4);
                Bs[rr][cc + q*4 + 0] = to_tf32(wv.x);
                Bs[rr][cc + q*4 + 1] = to_tf32(wv.y);
                Bs[rr][cc + q*4 + 2] = to_tf32(wv.z);
                Bs[rr][cc + q*4 + 3] = to_tf32(wv.w);
            }
        }
        __syncthreads();
#pragma unroll
        for (int kk = 0; kk < 32; kk += 8) {
            int ar = wr*16 + gid, ak = kk + qid;
            unsigned a0 = fu(As[ar][ak]),     a1 = fu(As[ar+8][ak]);
            unsigned a2 = fu(As[ar][ak+4]),   a3 = fu(As[ar+8][ak+4]);
#pragma unroll
            for (int j = 0; j < 4; j++) {
                int bn = wc*32 + j*8 + gid;
                unsigned b0 = fu(Bs[kk + qid][bn]);
                unsigned b1 = fu(Bs[kk + 4 + qid][bn]);
                mma_tf32(c[j], a0, a1, a2, a3, b0, b1);
            }
        }
        __syncthreads();
    }

    int r0 = wr*16 + gid, r1 = r0 + 8;
#pragma unroll
    for (int j = 0; j < 4; j++) {
        int n0 = c0 + wc*32 + j*8 + 2*qid;
        atomicAdd(&Z[(size_t)r0*N + n0],     c[j][0]);
        atomicAdd(&Z[(size_t)r0*N + n0 + 1], c[j][1]);
        atomicAdd(&Z[(size_t)r1*N + n0],     c[j][2]);
        atomicAdd(&Z[(size_t)r1*N + n0 + 1], c[j][3]);
    }
}

// -------- dual decoder projection: qdec = h0@Wq_dec, fdec = h0@Wf_dec --------
__global__ __launch_bounds__(256) void decproj_kernel(
    const float* __restrict__ h0,
    const float* __restrict__ Wq_dec, const float* __restrict__ Wf_dec,
    float* __restrict__ Zq, float* __restrict__ Zf) {
    const float* W = blockIdx.z ? Wf_dec : Wq_dec;
    float* Z = blockIdx.z ? Zf : Zq;
    mma32_body(h0, 512, W, 512, blockIdx.y*128, 128, Z, blockIdx.x*128);
}

// -------- LSTM gemm: z += x@lstm_kernel + h0@lstm_rec (grid 16x16) --------
__global__ __launch_bounds__(256) void lstm_gemm_kernel(
    const float* __restrict__ h0,
    const float* __restrict__ Wk, const float* __restrict__ Wrec,
    float* __restrict__ Z) {
    int y = blockIdx.y;
    if (y < 12) mma32_body(g_x, 1536, Wk,   2048, y*128,      128, Z, blockIdx.x*128);
    else        mma32_body(h0,  512,  Wrec, 2048, (y-12)*128, 128, Z, blockIdx.x*128);
}

// -------- readout gemm: r += h@Wr + x@Ur + qvec@Vr (grid 8x20) --------
__global__ __launch_bounds__(256) void readout_gemm_kernel(
    const float* __restrict__ Wr, const float* __restrict__ Ur,
    const float* __restrict__ Vr, float* __restrict__ Z) {
    int y = blockIdx.y;
    if (y < 4)       mma32_body(g_h,        512,  Wr, 1024, y*128,      128, Z, blockIdx.x*128);
    else if (y < 16) mma32_body(g_x,        1536, Ur, 1024, (y-4)*128,  128, Z, blockIdx.x*128);
    else             mma32_body(g_x + 1024, 1536, Vr, 1024, (y-16)*128, 128, Z, blockIdx.x*128);
}

// ======== merged, cp.async-pipelined tf32 score GEMM ========
__global__ __launch_bounds__(256) void score_kernel(
    const float* __restrict__ bq, const float* __restrict__ fe,
    const float* __restrict__ Wq, const float* __restrict__ Wf,
    const float* __restrict__ qdec, const float* __restrict__ fdec,
    const float* __restrict__ vq, const float* __restrict__ vf,
    float* __restrict__ qs, float* __restrict__ fs) {
    extern __shared__ float sm[];
    float* As = sm;                         // [2][64][AS_STRIDE]
    float* Bs = sm + AS_FLOATS;             // [2][32][BS_STRIDE]
    float* red = sm + AS_FLOATS + BS_FLOATS;

    const int bx = blockIdx.x;
    const float *X, *W, *dec, *v; float* scores; int rows_per_b, row0;
    if (bx < QBLKS) { X=bq; W=Wq; dec=qdec; v=vq; scores=qs; rows_per_b=LQd;      row0=bx*64; }
    else            { X=fe; W=Wf; dec=fdec; v=vf; scores=fs; rows_per_b=NFd*FLd; row0=(bx-QBLKS)*64; }
    const int col0 = blockIdx.y * 128;
    const int t = threadIdx.x;
    const int lane = t & 31;
    const int w = t >> 5;
    const int wr = w & 3;
    const int wc = w >> 2;
    const int gid = lane >> 2;
    const int qid = lane & 3;

    const int ar_ = t >> 3,  asg_ = (t & 7) * 4;
    const int br_ = t >> 5,  bsg_ = (t & 31) * 4;

    float c[8][4];
#pragma unroll
    for (int j = 0; j < 8; j++)
#pragma unroll
        for (int i = 0; i < 4; i++) c[j][i] = 0.f;

#define LOAD_STAGE(IT, BUF) do {                                              \
        int _k0 = (IT) * 32;                                                  \
        float* _a = As + (BUF)*64*AS_STRIDE;                                  \
        float* _b = Bs + (BUF)*32*BS_STRIDE;                                  \
        cp16(_a + ar_*AS_STRIDE + asg_,       X + (size_t)(row0+ar_)*512 + _k0 + asg_);        \
        cp16(_a + (ar_+32)*AS_STRIDE + asg_,  X + (size_t)(row0+ar_+32)*512 + _k0 + asg_);     \
        cp16(_b + br_*BS_STRIDE + bsg_,       W + (size_t)(_k0+br_)*512 + col0 + bsg_);        \
        cp16(_b + (br_+8)*BS_STRIDE + bsg_,   W + (size_t)(_k0+br_+8)*512 + col0 + bsg_);      \
        cp16(_b + (br_+16)*BS_STRIDE + bsg_,  W + (size_t)(_k0+br_+16)*512 + col0 + bsg_);     \
        cp16(_b + (br_+24)*BS_STRIDE + bsg_,  W + (size_t)(_k0+br_+24)*512 + col0 + bsg_);     \
        cp_commit();                                                          \
    } while (0)

    LOAD_STAGE(0, 0);
#pragma unroll 1
    for (int it = 0; it < 16; ++it) {
        int buf = it & 1;
        if (it + 1 < 16) { LOAD_STAGE(it + 1, (it + 1) & 1); cp_wait<1>(); }
        else             { cp_wait<0>(); }
        __syncthreads();
        const float* a = As + buf*64*AS_STRIDE;
        const float* b = Bs + buf*32*BS_STRIDE;
#pragma unroll
        for (int kk = 0; kk < 32; kk += 8) {
            int ar = wr*16 + gid, ak = kk + qid;
            unsigned a0 = fu(a[ar*AS_STRIDE + ak]);
            unsigned a1 = fu(a[(ar+8)*AS_STRIDE + ak]);
            unsigned a2 = fu(a[ar*AS_STRIDE + ak + 4]);
            unsigned a3 = fu(a[(ar+8)*AS_STRIDE + ak + 4]);
#pragma unroll
            for (int j = 0; j < 8; j++) {
                int bn = wc*64 + j*8 + gid;
                unsigned b0 = fu(b[(kk+qid)*BS_STRIDE + bn]);
                unsigned b1 = fu(b[(kk+4+qid)*BS_STRIDE + bn]);
                mma_tf32(c[j], a0, a1, a2, a3, b0, b1);
            }
        }
        __syncthreads();
    }
#undef LOAD_STAGE

    if (t < 64) red[t] = 0.f;
    __syncthreads();
    {
        int r0 = row0 + wr*16 + gid, r1 = r0 + 8;
        const float* dec0 = dec + (r0 / rows_per_b) * 512;
        const float* dec1 = dec + (r1 / rows_per_b) * 512;
        float s0 = 0.f, s1 = 0.f;
#pragma unroll
        for (int j = 0; j < 8; j++) {
            int n0 = col0 + wc*64 + j*8 + 2*qid;
            float vv0 = v[n0], vv1 = v[n0+1];
            s0 += tanhf(c[j][0] + dec0[n0]) * vv0 + tanhf(c[j][1] + dec0[n0+1]) * vv1;
            s1 += tanhf(c[j][2] + dec1[n0]) * vv0 + tanhf(c[j][3] + dec1[n0+1]) * vv1;
        }
        s0 += __shfl_xor_sync(0xffffffffu, s0, 1);
        s0 += __shfl_xor_sync(0xffffffffu, s0, 2);
        s1 += __shfl_xor_sync(0xffffffffu, s1, 1);
        s1 += __shfl_xor_sync(0xffffffffu, s1, 2);
        if (qid == 0) {
            atomicAdd(&red[wr*16 + gid], s0);
            atomicAdd(&red[wr*16 + gid + 8], s1);
        }
    }
    __syncthreads();
    if (t < 64) atomicAdd(&scores[(size_t)row0 + t], red[t]);
}

// ======== tf32 MMA vocab projection with fused maxout, coalesced Wy ========
// logits = maxout(g_r)[32,512] @ Wy[512,V] + by.
// Wy loader: col = t&127 fixed per thread, row walks (t>>7)+2q — each warp-op
// covers 32 consecutive columns = one 128B sector (fully coalesced, MLP=16).
// Vd odd -> scalar LDG (no wide-load alignment trap).
__global__ __launch_bounds__(256) void mma_vocab_kernel(
    const float* __restrict__ Wy, const float* __restrict__ by,
    float* __restrict__ out) {
    __shared__ float As[32][36];
    __shared__ float Bs[32][132];
    const int col0 = blockIdx.x * 128;
    const int t = threadIdx.x;
    const int lane = t & 31;
    const int w = t >> 5;
    const int wr = w & 1;
    const int wc = w >> 1;
    const int gid = lane >> 2;
    const int qid = lane & 3;
    // coalesced Wy loader coords
    const int lcol = t & 127;          // fixed column within tile
    const int lr0  = t >> 7;           // 0 or 1; rows lr0 + 2q
    const int cg   = col0 + lcol;
    const bool ok  = (cg < Vd);

    float c[4][4];
#pragma unroll
    for (int j = 0; j < 4; j++)
#pragma unroll
        for (int i = 0; i < 4; i++) c[j][i] = 0.f;

    for (int k0 = 0; k0 < 512; k0 += 32) {
        {   // A tile: fused maxout from g_r (pairs 2u, 2u+1), float4 reads
            int r = t >> 3, c4 = (t & 7) * 4;
            const float* pr = g_r + r*1024 + 2*(k0 + c4);
            float4 f0 = *(const float4*)pr;
            float4 f1 = *(const float4*)(pr + 4);
            As[r][c4+0] = to_tf32(fmaxf(f0.x, f0.y));
            As[r][c4+1] = to_tf32(fmaxf(f0.z, f0.w));
            As[r][c4+2] = to_tf32(fmaxf(f1.x, f1.y));
            As[r][c4+3] = to_tf32(fmaxf(f1.z, f1.w));
        }
        {   // Wy tile: 32x128, fully coalesced scalar loads
            const float* base = Wy + (size_t)(k0 + lr0)*Vd + cg;
#pragma unroll
            for (int q = 0; q < 16; q++)
                Bs[lr0 + 2*q][lcol] = ok ? to_tf32(__ldg(base + (size_t)(2*q)*Vd)) : 0.f;
        }
        __syncthreads();
#pragma unroll
        for (int kk = 0; kk < 32; kk += 8) {
            int ar = wr*16 + gid, ak = kk + qid;
            unsigned a0 = fu(As[ar][ak]),     a1 = fu(As[ar+8][ak]);
            unsigned a2 = fu(As[ar][ak+4]),   a3 = fu(As[ar+8][ak+4]);
#pragma unroll
            for (int j = 0; j < 4; j++) {
                int bn = wc*32 + j*8 + gid;
                unsigned b0 = fu(Bs[kk + qid][bn]);
                unsigned b1 = fu(Bs[kk + 4 + qid][bn]);
                mma_tf32(c[j], a0, a1, a2, a3, b0, b1);
            }
        }
        __syncthreads();
    }

    int r0 = wr*16 + gid, r1 = r0 + 8;
#pragma unroll
    for (int j = 0; j < 4; j++) {
        int n0 = col0 + wc*32 + j*8 + 2*qid;
        int n1 = n0 + 1;
        if (n0 < Vd) {
            float b = by[n0];
            out[r0*Vd + n0] = c[j][0] + b;
            out[r1*Vd + n0] = c[j][2] + b;
        }
        if (n1 < Vd) {
            float b = by[n1];
            out[r0*Vd + n1] = c[j][1] + b;
            out[r1*Vd + n1] = c[j][3] + b;
        }
    }
}

// -------- selection (rank-based with packed 64-bit keys) --------
__global__ __launch_bounds__(512) void select_kernel(float* __restrict__ out) {
    int t = threadIdx.x, lane = t & 31, w = t >> 5;
    if (blockIdx.x < 32) {
        int b = blockIdx.x;
        if (w == 0) {
            float v0 = g_qscore[b*64 + lane], v1 = g_qscore[b*64 + lane + 32];
            out[OFF_QLOG + b*64 + lane]      = v0;
            out[OFF_QLOG + b*64 + lane + 32] = v1;
            float mx = fmaxf(v0, v1);
#pragma unroll
            for (int o = 16; o; o >>= 1) mx = fmaxf(mx, __shfl_xor_sync(0xffffffffu, mx, o));
            float e0 = expf(v0 - mx), e1 = expf(v1 - mx);
            float s = e0 + e1;
#pragma unroll
            for (int o = 16; o; o >>= 1) s += __shfl_xor_sync(0xffffffffu, s, o);
            float inv = 1.f / s;
            g_qw[b*64 + lane]      = e0 * inv;
            g_qw[b*64 + lane + 32] = e1 * inv;
        }
    } else {
        int b = blockIdx.x - 32;
        __shared__ unsigned long long key[400];
        __shared__ float sc[400];
        __shared__ float warpmax[16];
        __shared__ float s_mx, s_sum;
        __shared__ int s_cnt;
        for (int i = t; i < 400; i += 512) {
            float v = g_fscore[b*400 + i];
            sc[i] = v;
            unsigned u = __float_as_uint(v);
            u = (u & 0x80000000u) ? ~u : (u | 0x80000000u);   // monotone float->uint
            key[i] = ((unsigned long long)u << 32) | (unsigned)(399 - i);
        }
        if (t == 0) { s_cnt = 0; s_sum = 0.f; }
        __syncthreads();
        float m = -1e38f;
        for (int i = t; i < 400; i += 512) m = fmaxf(m, sc[i]);
#pragma unroll
        for (int o = 16; o; o >>= 1) m = fmaxf(m, __shfl_xor_sync(0xffffffffu, m, o));
        if (lane == 0) warpmax[w] = m;
        __syncthreads();
        if (t == 0) {
            float mm = warpmax[0];
#pragma unroll
            for (int ww = 1; ww < 16; ww++) mm = fmaxf(mm, warpmax[ww]);
            s_mx = mm;
        }
        __syncthreads();
        float mx = s_mx;
        int slot = -1; float e = 0.f;
        if (t < 400) {
            unsigned long long mykey = key[t];
            int r = 0;
#pragma unroll 8
            for (int j = 0; j < 400; j++) r += (key[j] > mykey);
            if (r < 40) {
                slot = atomicAdd(&s_cnt, 1);
                e = expf(sc[t] - mx);
                atomicAdd(&s_sum, e);
                g_tidx[b*40 + slot] = t;
            }
        }
        __syncthreads();
        if (slot >= 0) g_tw[b*40 + slot] = e / s_sum;
    }
}

// -------- gather: weighted sums, wide grid for latency hiding --------
__global__ __launch_bounds__(128) void gather_kernel(
    const float* __restrict__ bq, const float* __restrict__ fe,
    float* __restrict__ out) {
    int e = blockIdx.x * 128 + threadIdx.x;
    if (blockIdx.y < 32) {
        int b = blockIdx.y;
        const float* wp = g_qw + b*64;
        const float* src = bq + (size_t)b*64*512 + e;
        float s = 0.f;
#pragma unroll 8
        for (int l = 0; l < 64; l++) s += wp[l] * src[l*512];
        g_x[b*1536 + 1024 + e] = s;
        out[OFF_QVEC + b*512 + e] = s;
    } else {
        int b = blockIdx.y - 32;
        __shared__ float tw[40]; __shared__ int tix[40];
        if (threadIdx.x < 40) {
            tw[threadIdx.x]  = g_tw[b*40 + threadIdx.x];
            tix[threadIdx.x] = g_tidx[b*40 + threadIdx.x];
        }
        __syncthreads();
        const float* src = fe + (size_t)b*400*512 + e;
        float s = 0.f;
#pragma unroll 8
        for (int k = 0; k < 40; k++) s += tw[k] * src[(size_t)tix[k]*512];
        g_x[b*1536 + 512 + e] = s;
    }
}

// -------- LSTM gates --------
__global__ void gates_kernel(const float* __restrict__ c0, float* __restrict__ out) {
    int i = blockIdx.x * 256 + threadIdx.x;
    if (i >= BB*Hd) return;
    int b = i >> 9, u = i & 511;
    const float* zb = g_z + b*2048;
    float zi = zb[u], zf = zb[512 + u], zg = zb[1024 + u], zo = zb[1536 + u];
    float si = 1.f / (1.f + expf(-zi));
    float sf = 1.f / (1.f + expf(-zf));
    float so = 1.f / (1.f + expf(-zo));
    float cc = sf * c0[i] + si * tanhf(zg);
    float hh = so * tanhf(cc);
    out[OFF_H + i] = hh;
    out[OFF_C + i] = cc;
    g_h[i] = hh;
}

extern "C" void kernel_launch(void* const* d_in, const int* in_sizes, int n_in,
                              void* d_out, int out_size) {
    const float* bq        = (const float*)d_in[0];
    const float* fe        = (const float*)d_in[1];
    const float* h0        = (const float*)d_in[2];
    const float* c0        = (const float*)d_in[3];
    const float* prev_emb  = (const float*)d_in[4];
    const float* Wq_enc    = (const float*)d_in[5];
    const float* Wq_dec    = (const float*)d_in[6];
    const float* vq        = (const float*)d_in[7];
    const float* Wf_enc    = (const float*)d_in[8];
    const float* Wf_dec    = (const float*)d_in[9];
    const float* vf        = (const float*)d_in[10];
    const float* lstm_kernel = (const float*)d_in[11];
    const float* lstm_rec    = (const float*)d_in[12];
    const float* lstm_bias   = (const float*)d_in[13];
    const float* Wr        = (const float*)d_in[14];
    const float* br        = (const float*)d_in[15];
    const float* Ur        = (const float*)d_in[16];
    const float* bu        = (const float*)d_in[17];
    const float* Vr        = (const float*)d_in[18];
    const float* bv        = (const float*)d_in[19];
    const float* Wy        = (const float*)d_in[20];
    const float* by        = (const float*)d_in[21];
    float* out = (float*)d_out;

    float *p_qdec, *p_fdec, *p_z, *p_r, *p_qs, *p_fs;
    cudaGetSymbolAddress((void**)&p_qdec, g_qdec);
    cudaGetSymbolAddress((void**)&p_fdec, g_fdec);
    cudaGetSymbolAddress((void**)&p_z,    g_z);
    cudaGetSymbolAddress((void**)&p_r,    g_r);
    cudaGetSymbolAddress((void**)&p_qs,   g_qscore);
    cudaGetSymbolAddress((void**)&p_fs,   g_fscore);

    static int smem_set = 0;
    if (!smem_set) {
        cudaFuncSetAttribute(score_kernel,
                             cudaFuncAttributeMaxDynamicSharedMemorySize,
                             SCORE_SMEM_BYTES);
        smem_set = 1;
    }

    prep_kernel<<<256, 256>>>(prev_emb, lstm_bias, br, bu, bv);

    // decoder-state projections (one launch, z selects Wq_dec/Wf_dec)
    decproj_kernel<<<dim3(4, 4, 2), 256>>>(h0, Wq_dec, Wf_dec, p_qdec, p_fdec);

    // merged, pipelined attention-score GEMM (tf32 tensor cores + cp.async)
    score_kernel<<<dim3(QBLKS + FBLKS, 4), 256, SCORE_SMEM_BYTES>>>(
        bq, fe, Wq_enc, Wf_enc, p_qdec, p_fdec, vq, vf, p_qs, p_fs);

    // attention pooling: rank-based selection (packed keys), then gather
    select_kernel<<<64, 512>>>(out);
    gather_kernel<<<dim3(4, 64), 128>>>(bq, fe, out);

    // LSTM: z = x@Wk + h0@Wrec + bias (one launch, tf32 MMA)
    lstm_gemm_kernel<<<dim3(16, 16), 256>>>(h0, lstm_kernel, lstm_rec, p_z);
    gates_kernel<<<64, 256>>>(c0, out);

    // readout: r = h@Wr + x@Ur + qvec@Vr + biases (one launch, tf32 MMA)
    readout_gemm_kernel<<<dim3(8, 20), 256>>>(Wr, Ur, Vr, p_r);

    // vocab projection (tf32, fused maxout, coalesced Wy loader)
    mma_vocab_kernel<<<(Vd + 127)/128, 256>>>(Wy, by, out);
}

// round 16
// speedup vs baseline: 1.3949x; 1.3949x over previous
#include <cuda_runtime.h>
#include <math.h>

#define BB 32
#define LQd 64
#define Ed 512
#define NFd 10
#define FLd 40
#define Dd 512
#define Hd 512
#define Ad 512
#define Rd 1024
#define Vd 50257

#define MQ (BB*LQd)        // 2048 rows
#define MF (BB*NFd*FLd)    // 12800 rows
#define QB2 (MQ/128)       // 16 question blocks (128-row tiles)
#define FB2 (MF/128)       // 100 facts blocks

// output offsets (flattened tuple: logits, h, c, q_vec, q_logits)
#define OFF_H     (BB*Vd)
#define OFF_C     (OFF_H + BB*Hd)
#define OFF_QVEC  (OFF_C + BB*Hd)
#define OFF_QLOG  (OFF_QVEC + BB*Ed)

// score-kernel dynamic smem layout (floats): 128-row A tile
#define AS_STRIDE 36        // 144B rows: 16B-aligned, conflict-free
#define BS_STRIDE 136       // 544B rows: 16B-aligned, conflict-free
#define AS_FLOATS (2*128*AS_STRIDE)
#define BS_FLOATS (2*32*BS_STRIDE)
#define SCORE_SMEM_BYTES ((AS_FLOATS + BS_FLOATS + 128)*4)

// -------- scratch (device globals; no allocation allowed) --------
__device__ float g_qscore[MQ];
__device__ float g_fscore[MF];
__device__ float g_qdec[BB*Ad];
__device__ float g_fdec[BB*Ad];
__device__ float g_x[BB*1536];     // [prev_emb | f_vec | q_vec]
__device__ float g_z[BB*2048];
__device__ float g_r[BB*Rd];
__device__ float g_h[BB*Hd];
__device__ float g_m[BB*(Rd/2)];
__device__ float g_qw[MQ];         // question softmax weights
__device__ int   g_tidx[BB*40];    // facts top-k indices (unordered)
__device__ float g_tw[BB*40];      // facts top-k softmax weights

// -------- helpers --------
__device__ __forceinline__ float to_tf32(float x) {
    unsigned u;
    asm("cvt.rna.tf32.f32 %0, %1;" : "=r"(u) : "f"(x));
    return __uint_as_float(u);
}
__device__ __forceinline__ unsigned fu(float x) { return __float_as_uint(x); }

__device__ __forceinline__ void mma_tf32(float c[4],
    unsigned a0, unsigned a1, unsigned a2, unsigned a3,
    unsigned b0, unsigned b1) {
    asm volatile(
        "mma.sync.aligned.m16n8k8.row.col.f32.tf32.tf32.f32 "
        "{%0,%1,%2,%3},{%4,%5,%6,%7},{%8,%9},{%0,%1,%2,%3};\n"
        : "+f"(c[0]), "+f"(c[1]), "+f"(c[2]), "+f"(c[3])
        : "r"(a0), "r"(a1), "r"(a2), "r"(a3), "r"(b0), "r"(b1));
}

__device__ __forceinline__ void cp16(void* s, const void* g) {
    unsigned sa = (unsigned)__cvta_generic_to_shared(s);
    asm volatile("cp.async.ca.shared.global [%0], [%1], 16;\n" :: "r"(sa), "l"(g));
}
__device__ __forceinline__ void cp_commit() {
    asm volatile("cp.async.commit_group;\n");
}
template<int N> __device__ __forceinline__ void cp_wait() {
    asm volatile("cp.async.wait_group %0;\n" :: "n"(N));
}

// -------- prep: zero accumulators, seed biases, copy prev_emb --------
__global__ void prep_kernel(const float* __restrict__ prev_emb,
                            const float* __restrict__ lstm_bias,
                            const float* __restrict__ br,
                            const float* __restrict__ bu,
                            const float* __restrict__ bv) {
    int i = blockIdx.x * 256 + threadIdx.x;   // grid covers 65536
    if (i < MQ)      g_qscore[i] = 0.f;
    if (i < MF)      g_fscore[i] = 0.f;
    if (i < BB*Ad)   { g_qdec[i] = 0.f; g_fdec[i] = 0.f; }
    if (i < BB*Ed)   { int b = i >> 9, e = i & 511; g_x[b*1536 + e] = prev_emb[i]; }
    if (i < BB*2048) g_z[i] = lstm_bias[i & 2047];
    if (i < BB*Rd)   { int u = i & 1023; g_r[i] = br[u] + bu[u] + bv[u]; }
}

// -------- tf32 MMA 32-row GEMM accumulator body (proven R12 form) --------
__device__ __forceinline__ void mma32_body(
    const float* __restrict__ X, int lda, const float* __restrict__ W,
    int N, int kbase, int kchunk, float* __restrict__ Z, int c0) {
    __shared__ float As[32][36];
    __shared__ float Bs[32][132];
    const int t = threadIdx.x;
    const int lane = t & 31;
    const int w = t >> 5;
    const int wr = w & 1;
    const int wc = w >> 1;
    const int gid = lane >> 2;
    const int qid = lane & 3;

    float c[4][4];
#pragma unroll
    for (int j = 0; j < 4; j++)
#pragma unroll
        for (int i = 0; i < 4; i++) c[j][i] = 0.f;

    for (int k0 = kbase; k0 < kbase + kchunk; k0 += 32) {
        {   int r = t >> 3, cg = (t & 7) * 4;
            float4 v0 = *(const float4*)(X + (size_t)r*lda + k0 + cg);
            As[r][cg+0] = to_tf32(v0.x); As[r][cg+1] = to_tf32(v0.y);
            As[r][cg+2] = to_tf32(v0.z); As[r][cg+3] = to_tf32(v0.w);
        }
        {   int rr = t >> 3, cc = (t & 7) * 16;
            const float* src = W + (size_t)(k0 + rr)*N + c0 + cc;
#pragma unroll
            for (int q = 0; q < 4; q++) {
                float4 wv = *(const float4*)(src + q*4);
                Bs[rr][cc + q*4 + 0] = to_tf32(wv.x);
                Bs[rr][cc + q*4 + 1] = to_tf32(wv.y);
                Bs[rr][cc + q*4 + 2] = to_tf32(wv.z);
                Bs[rr][cc + q*4 + 3] = to_tf32(wv.w);
            }
        }
        __syncthreads();
#pragma unroll
        for (int kk = 0; kk < 32; kk += 8) {
            int ar = wr*16 + gid, ak = kk + qid;
            unsigned a0 = fu(As[ar][ak]),     a1 = fu(As[ar+8][ak]);
            unsigned a2 = fu(As[ar][ak+4]),   a3 = fu(As[ar+8][ak+4]);
#pragma unroll
            for (int j = 0; j < 4; j++) {
                int bn = wc*32 + j*8 + gid;
                unsigned b0 = fu(Bs[kk + qid][bn]);
                unsigned b1 = fu(Bs[kk + 4 + qid][bn]);
                mma_tf32(c[j], a0, a1, a2, a3, b0, b1);
            }
        }
        __syncthreads();
    }

    int r0 = wr*16 + gid, r1 = r0 + 8;
#pragma unroll
    for (int j = 0; j < 4; j++) {
        int n0 = c0 + wc*32 + j*8 + 2*qid;
        atomicAdd(&Z[(size_t)r0*N + n0],     c[j][0]);
        atomicAdd(&Z[(size_t)r0*N + n0 + 1], c[j][1]);
        atomicAdd(&Z[(size_t)r1*N + n0],     c[j][2]);
        atomicAdd(&Z[(size_t)r1*N + n0 + 1], c[j][3]);
    }
}

// -------- dual decoder projection --------
__global__ __launch_bounds__(256) void decproj_kernel(
    const float* __restrict__ h0,
    const float* __restrict__ Wq_dec, const float* __restrict__ Wf_dec,
    float* __restrict__ Zq, float* __restrict__ Zf) {
    const float* W = blockIdx.z ? Wf_dec : Wq_dec;
    float* Z = blockIdx.z ? Zf : Zq;
    mma32_body(h0, 512, W, 512, blockIdx.y*128, 128, Z, blockIdx.x*128);
}

// -------- LSTM gemm --------
__global__ __launch_bounds__(256) void lstm_gemm_kernel(
    const float* __restrict__ h0,
    const float* __restrict__ Wk, const float* __restrict__ Wrec,
    float* __restrict__ Z) {
    int y = blockIdx.y;
    if (y < 12) mma32_body(g_x, 1536, Wk,   2048, y*128,      128, Z, blockIdx.x*128);
    else        mma32_body(h0,  512,  Wrec, 2048, (y-12)*128, 128, Z, blockIdx.x*128);
}

// -------- readout gemm --------
__global__ __launch_bounds__(256) void readout_gemm_kernel(
    const float* __restrict__ Wr, const float* __restrict__ Ur,
    const float* __restrict__ Vr, float* __restrict__ Z) {
    int y = blockIdx.y;
    if (y < 4)       mma32_body(g_h,        512,  Wr, 1024, y*128,      128, Z, blockIdx.x*128);
    else if (y < 16) mma32_body(g_x,        1536, Ur, 1024, (y-4)*128,  128, Z, blockIdx.x*128);
    else             mma32_body(g_x + 1024, 1536, Vr, 1024, (y-16)*128, 128, Z, blockIdx.x*128);
}

// ======== score GEMM: 128-row tiles, cp.async pipelined tf32 ========
// Each warp: 32 rows (2 m16 fragments) x 64 cols -> B fragments amortized
// over 2 row-fragments (LDS/MMA 2.5 -> 1.5).
__global__ __launch_bounds__(256) void score_kernel(
    const float* __restrict__ bq, const float* __restrict__ fe,
    const float* __restrict__ Wq, const float* __restrict__ Wf,
    const float* __restrict__ qdec, const float* __restrict__ fdec,
    const float* __restrict__ vq, const float* __restrict__ vf,
    float* __restrict__ qs, float* __restrict__ fs) {
    extern __shared__ float sm[];
    float* As = sm;                         // [2][128][AS_STRIDE]
    float* Bs = sm + AS_FLOATS;             // [2][32][BS_STRIDE]
    float* red = sm + AS_FLOATS + BS_FLOATS;

    const int bx = blockIdx.x;
    const float *X, *W, *dec, *v; float* scores; int rows_per_b, row0;
    if (bx < QB2) { X=bq; W=Wq; dec=qdec; v=vq; scores=qs; rows_per_b=LQd;      row0=bx*128; }
    else          { X=fe; W=Wf; dec=fdec; v=vf; scores=fs; rows_per_b=NFd*FLd; row0=(bx-QB2)*128; }
    const int col0 = blockIdx.y * 128;
    const int t = threadIdx.x;
    const int lane = t & 31;
    const int w = t >> 5;
    const int wr = w & 3;          // 4 row groups of 32
    const int wc = w >> 2;         // 2 col groups of 64
    const int gid = lane >> 2;
    const int qid = lane & 3;

    // loaders: A 128x32 = 1024 chunks (4/thread), B 32x128 = 1024 (4/thread)
    const int ar_ = t >> 3,  asg_ = (t & 7) * 4;   // A rows ar_+32k, col asg_
    const int br_ = t >> 5,  bsg_ = (t & 31) * 4;  // B rows br_+8k

    float c[2][8][4];
#pragma unroll
    for (int g = 0; g < 2; g++)
#pragma unroll
        for (int j = 0; j < 8; j++)
#pragma unroll
            for (int i = 0; i < 4; i++) c[g][j][i] = 0.f;

#define LOAD_STAGE(IT, BUF) do {                                              \
        int _k0 = (IT) * 32;                                                  \
        float* _a = As + (BUF)*128*AS_STRIDE;                                 \
        float* _b = Bs + (BUF)*32*BS_STRIDE;                                  \
        cp16(_a + ar_*AS_STRIDE + asg_,       X + (size_t)(row0+ar_)*512 + _k0 + asg_);        \
        cp16(_a + (ar_+32)*AS_STRIDE + asg_,  X + (size_t)(row0+ar_+32)*512 + _k0 + asg_);     \
        cp16(_a + (ar_+64)*AS_STRIDE + asg_,  X + (size_t)(row0+ar_+64)*512 + _k0 + asg_);     \
        cp16(_a + (ar_+96)*AS_STRIDE + asg_,  X + (size_t)(row0+ar_+96)*512 + _k0 + asg_);     \
        cp16(_b + br_*BS_STRIDE + bsg_,       W + (size_t)(_k0+br_)*512 + col0 + bsg_);        \
        cp16(_b + (br_+8)*BS_STRIDE + bsg_,   W + (size_t)(_k0+br_+8)*512 + col0 + bsg_);      \
        cp16(_b + (br_+16)*BS_STRIDE + bsg_,  W + (size_t)(_k0+br_+16)*512 + col0 + bsg_);     \
        cp16(_b + (br_+24)*BS_STRIDE + bsg_,  W + (size_t)(_k0+br_+24)*512 + col0 + bsg_);     \
        cp_commit();                                                          \
    } while (0)

    LOAD_STAGE(0, 0);
#pragma unroll 1
    for (int it = 0; it < 16; ++it) {
        int buf = it & 1;
        if (it + 1 < 16) { LOAD_STAGE(it + 1, (it + 1) & 1); cp_wait<1>(); }
        else             { cp_wait<0>(); }
        __syncthreads();
        const float* a = As + buf*128*AS_STRIDE;
        const float* b = Bs + buf*32*BS_STRIDE;
#pragma unroll
        for (int kk = 0; kk < 32; kk += 8) {
            int ak = kk + qid;
            unsigned af[2][4];
#pragma unroll
            for (int g = 0; g < 2; g++) {
                int ar = wr*32 + g*16 + gid;
                af[g][0] = fu(a[ar*AS_STRIDE + ak]);
                af[g][1] = fu(a[(ar+8)*AS_STRIDE + ak]);
                af[g][2] = fu(a[ar*AS_STRIDE + ak + 4]);
                af[g][3] = fu(a[(ar+8)*AS_STRIDE + ak + 4]);
            }
#pragma unroll
            for (int j = 0; j < 8; j++) {
                int bn = wc*64 + j*8 + gid;
                unsigned b0 = fu(b[(kk+qid)*BS_STRIDE + bn]);
                unsigned b1 = fu(b[(kk+4+qid)*BS_STRIDE + bn]);
                mma_tf32(c[0][j], af[0][0], af[0][1], af[0][2], af[0][3], b0, b1);
                mma_tf32(c[1][j], af[1][0], af[1][1], af[1][2], af[1][3], b0, b1);
            }
        }
        __syncthreads();
    }
#undef LOAD_STAGE

    if (t < 128) red[t] = 0.f;
    __syncthreads();
#pragma unroll
    for (int g = 0; g < 2; g++) {
        int r0 = row0 + wr*32 + g*16 + gid, r1 = r0 + 8;
        const float* dec0 = dec + (r0 / rows_per_b) * 512;
        const float* dec1 = dec + (r1 / rows_per_b) * 512;
        float s0 = 0.f, s1 = 0.f;
#pragma unroll
        for (int j = 0; j < 8; j++) {
            int n0 = col0 + wc*64 + j*8 + 2*qid;
            float vv0 = v[n0], vv1 = v[n0+1];
            s0 += tanhf(c[g][j][0] + dec0[n0]) * vv0 + tanhf(c[g][j][1] + dec0[n0+1]) * vv1;
            s1 += tanhf(c[g][j][2] + dec1[n0]) * vv0 + tanhf(c[g][j][3] + dec1[n0+1]) * vv1;
        }
        s0 += __shfl_xor_sync(0xffffffffu, s0, 1);
        s0 += __shfl_xor_sync(0xffffffffu, s0, 2);
        s1 += __shfl_xor_sync(0xffffffffu, s1, 1);
        s1 += __shfl_xor_sync(0xffffffffu, s1, 2);
        if (qid == 0) {
            atomicAdd(&red[wr*32 + g*16 + gid], s0);
            atomicAdd(&red[wr*32 + g*16 + gid + 8], s1);
        }
    }
    __syncthreads();
    if (t < 128) atomicAdd(&scores[(size_t)row0 + t], red[t]);
}

// ======== tf32 MMA vocab projection (R10/R12 proven form) ========
__global__ __launch_bounds__(256) void mma_vocab_kernel(
    const float* __restrict__ Wy, const float* __restrict__ by,
    float* __restrict__ out) {
    __shared__ float As[32][36];
    __shared__ float Bs[32][132];
    const int col0 = blockIdx.x * 128;
    const int t = threadIdx.x;
    const int lane = t & 31;
    const int w = t >> 5;
    const int wr = w & 1;
    const int wc = w >> 1;
    const int gid = lane >> 2;
    const int qid = lane & 3;

    float c[4][4];
#pragma unroll
    for (int j = 0; j < 4; j++)
#pragma unroll
        for (int i = 0; i < 4; i++) c[j][i] = 0.f;

    for (int k0 = 0; k0 < 512; k0 += 32) {
        {   int r = t >> 3, cg = (t & 7) * 4;
            float4 v0 = *(const float4*)(g_m + r*512 + k0 + cg);
            As[r][cg+0] = to_tf32(v0.x); As[r][cg+1] = to_tf32(v0.y);
            As[r][cg+2] = to_tf32(v0.z); As[r][cg+3] = to_tf32(v0.w);
        }
        {   int rr = t >> 3, cc = (t & 7) * 16;
            const float* src = Wy + (size_t)(k0 + rr)*Vd;
#pragma unroll
            for (int i = 0; i < 16; i++) {
                int cg = col0 + cc + i;
                Bs[rr][cc + i] = (cg < Vd) ? to_tf32(__ldg(src + cg)) : 0.f;
            }
        }
        __syncthreads();
#pragma unroll
        for (int kk = 0; kk < 32; kk += 8) {
            int ar = wr*16 + gid, ak = kk + qid;
            unsigned a0 = fu(As[ar][ak]),     a1 = fu(As[ar+8][ak]);
            unsigned a2 = fu(As[ar][ak+4]),   a3 = fu(As[ar+8][ak+4]);
#pragma unroll
            for (int j = 0; j < 4; j++) {
                int bn = wc*32 + j*8 + gid;
                unsigned b0 = fu(Bs[kk + qid][bn]);
                unsigned b1 = fu(Bs[kk + 4 + qid][bn]);
                mma_tf32(c[j], a0, a1, a2, a3, b0, b1);
            }
        }
        __syncthreads();
    }

    int r0 = wr*16 + gid, r1 = r0 + 8;
#pragma unroll
    for (int j = 0; j < 4; j++) {
        int n0 = col0 + wc*32 + j*8 + 2*qid;
        int n1 = n0 + 1;
        if (n0 < Vd) {
            float b = by[n0];
            out[r0*Vd + n0] = c[j][0] + b;
            out[r1*Vd + n0] = c[j][2] + b;
        }
        if (n1 < Vd) {
            float b = by[n1];
            out[r0*Vd + n1] = c[j][1] + b;
            out[r1*Vd + n1] = c[j][3] + b;
        }
    }
}

// -------- selection (rank-based with packed 64-bit keys) --------
__global__ __launch_bounds__(512) void select_kernel(float* __restrict__ out) {
    int t = threadIdx.x, lane = t & 31, w = t >> 5;
    if (blockIdx.x < 32) {
        int b = blockIdx.x;
        if (w == 0) {
            float v0 = g_qscore[b*64 + lane], v1 = g_qscore[b*64 + lane + 32];
            out[OFF_QLOG + b*64 + lane]      = v0;
            out[OFF_QLOG + b*64 + lane + 32] = v1;
            float mx = fmaxf(v0, v1);
#pragma unroll
            for (int o = 16; o; o >>= 1) mx = fmaxf(mx, __shfl_xor_sync(0xffffffffu, mx, o));
            float e0 = expf(v0 - mx), e1 = expf(v1 - mx);
            float s = e0 + e1;
#pragma unroll
            for (int o = 16; o; o >>= 1) s += __shfl_xor_sync(0xffffffffu, s, o);
            float inv = 1.f / s;
            g_qw[b*64 + lane]      = e0 * inv;
            g_qw[b*64 + lane + 32] = e1 * inv;
        }
    } else {
        int b = blockIdx.x - 32;
        __shared__ unsigned long long key[400];
        __shared__ float sc[400];
        __shared__ float warpmax[16];
        __shared__ float s_mx, s_sum;
        __shared__ int s_cnt;
        for (int i = t; i < 400; i += 512) {
            float v = g_fscore[b*400 + i];
            sc[i] = v;
            unsigned u = __float_as_uint(v);
            u = (u & 0x80000000u) ? ~u : (u | 0x80000000u);   // monotone float->uint
            key[i] = ((unsigned long long)u << 32) | (unsigned)(399 - i);
        }
        if (t == 0) { s_cnt = 0; s_sum = 0.f; }
        __syncthreads();
        float m = -1e38f;
        for (int i = t; i < 400; i += 512) m = fmaxf(m, sc[i]);
#pragma unroll
        for (int o = 16; o; o >>= 1) m = fmaxf(m, __shfl_xor_sync(0xffffffffu, m, o));
        if (lane == 0) warpmax[w] = m;
        __syncthreads();
        if (t == 0) {
            float mm = warpmax[0];
#pragma unroll
            for (int ww = 1; ww < 16; ww++) mm = fmaxf(mm, warpmax[ww]);
            s_mx = mm;
        }
        __syncthreads();
        float mx = s_mx;
        int slot = -1; float e = 0.f;
        if (t < 400) {
            unsigned long long mykey = key[t];
            int r = 0;
#pragma unroll 8
            for (int j = 0; j < 400; j++) r += (key[j] > mykey);
            if (r < 40) {
                slot = atomicAdd(&s_cnt, 1);
                e = expf(sc[t] - mx);
                atomicAdd(&s_sum, e);
                g_tidx[b*40 + slot] = t;
            }
        }
        __syncthreads();
        if (slot >= 0) g_tw[b*40 + slot] = e / s_sum;
    }
}

// -------- gather: weighted sums, wide grid for latency hiding --------
__global__ __launch_bounds__(128) void gather_kernel(
    const float* __restrict__ bq, const float* __restrict__ fe,
    float* __restrict__ out) {
    int e = blockIdx.x * 128 + threadIdx.x;
    if (blockIdx.y < 32) {
        int b = blockIdx.y;
        const float* wp = g_qw + b*64;
        const float* src = bq + (size_t)b*64*512 + e;
        float s = 0.f;
#pragma unroll 8
        for (int l = 0; l < 64; l++) s += wp[l] * src[l*512];
        g_x[b*1536 + 1024 + e] = s;
        out[OFF_QVEC + b*512 + e] = s;
    } else {
        int b = blockIdx.y - 32;
        __shared__ float tw[40]; __shared__ int tix[40];
        if (threadIdx.x < 40) {
            tw[threadIdx.x]  = g_tw[b*40 + threadIdx.x];
            tix[threadIdx.x] = g_tidx[b*40 + threadIdx.x];
        }
        __syncthreads();
        const float* src = fe + (size_t)b*400*512 + e;
        float s = 0.f;
#pragma unroll 8
        for (int k = 0; k < 40; k++) s += tw[k] * src[(size_t)tix[k]*512];
        g_x[b*1536 + 512 + e] = s;
    }
}

// -------- LSTM gates --------
__global__ void gates_kernel(const float* __restrict__ c0, float* __restrict__ out) {
    int i = blockIdx.x * 256 + threadIdx.x;
    if (i >= BB*Hd) return;
    int b = i >> 9, u = i & 511;
    const float* zb = g_z + b*2048;
    float zi = zb[u], zf = zb[512 + u], zg = zb[1024 + u], zo = zb[1536 + u];
    float si = 1.f / (1.f + expf(-zi));
    float sf = 1.f / (1.f + expf(-zf));
    float so = 1.f / (1.f + expf(-zo));
    float cc = sf * c0[i] + si * tanhf(zg);
    float hh = so * tanhf(cc);
    out[OFF_H + i] = hh;
    out[OFF_C + i] = cc;
    g_h[i] = hh;
}

// -------- maxout over consecutive pairs --------
__global__ void maxout_kernel() {
    int i = blockIdx.x * 256 + threadIdx.x;
    if (i >= BB*512) return;
    int b = i >> 9, u = i & 511;
    g_m[i] = fmaxf(g_r[b*1024 + 2*u], g_r[b*1024 + 2*u + 1]);
}

extern "C" void kernel_launch(void* const* d_in, const int* in_sizes, int n_in,
                              void* d_out, int out_size) {
    const float* bq        = (const float*)d_in[0];
    const float* fe        = (const float*)d_in[1];
    const float* h0        = (const float*)d_in[2];
    const float* c0        = (const float*)d_in[3];
    const float* prev_emb  = (const float*)d_in[4];
    const float* Wq_enc    = (const float*)d_in[5];
    const float* Wq_dec    = (const float*)d_in[6];
    const float* vq        = (const float*)d_in[7];
    const float* Wf_enc    = (const float*)d_in[8];
    const float* Wf_dec    = (const float*)d_in[9];
    const float* vf        = (const float*)d_in[10];
    const float* lstm_kernel = (const float*)d_in[11];
    const float* lstm_rec    = (const float*)d_in[12];
    const float* lstm_bias   = (const float*)d_in[13];
    const float* Wr        = (const float*)d_in[14];
    const float* br        = (const float*)d_in[15];
    const float* Ur        = (const float*)d_in[16];
    const float* bu        = (const float*)d_in[17];
    const float* Vr        = (const float*)d_in[18];
    const float* bv        = (const float*)d_in[19];
    const float* Wy        = (const float*)d_in[20];
    const float* by        = (const float*)d_in[21];
    float* out = (float*)d_out;

    float *p_qdec, *p_fdec, *p_z, *p_r, *p_qs, *p_fs;
    cudaGetSymbolAddress((void**)&p_qdec, g_qdec);
    cudaGetSymbolAddress((void**)&p_fdec, g_fdec);
    cudaGetSymbolAddress((void**)&p_z,    g_z);
    cudaGetSymbolAddress((void**)&p_r,    g_r);
    cudaGetSymbolAddress((void**)&p_qs,   g_qscore);
    cudaGetSymbolAddress((void**)&p_fs,   g_fscore);

    static int smem_set = 0;
    if (!smem_set) {
        cudaFuncSetAttribute(score_kernel,
                             cudaFuncAttributeMaxDynamicSharedMemorySize,
                             SCORE_SMEM_BYTES);
        smem_set = 1;
    }

    prep_kernel<<<256, 256>>>(prev_emb, lstm_bias, br, bu, bv);

    // decoder-state projections (one launch, z selects Wq_dec/Wf_dec)
    decproj_kernel<<<dim3(4, 4, 2), 256>>>(h0, Wq_dec, Wf_dec, p_qdec, p_fdec);

    // merged, pipelined attention-score GEMM (128-row tiles)
    score_kernel<<<dim3(QB2 + FB2, 4), 256, SCORE_SMEM_BYTES>>>(
        bq, fe, Wq_enc, Wf_enc, p_qdec, p_fdec, vq, vf, p_qs, p_fs);

    // attention pooling: rank-based selection (packed keys), then gather
    select_kernel<<<64, 512>>>(out);
    gather_kernel<<<dim3(4, 64), 128>>>(bq, fe, out);

    // LSTM: z = x@Wk + h0@Wrec + bias (one launch, tf32 MMA)
    lstm_gemm_kernel<<<dim3(16, 16), 256>>>(h0, lstm_kernel, lstm_rec, p_z);
    gates_kernel<<<64, 256>>>(c0, out);

    // readout: r = h@Wr + x@Ur + qvec@Vr + biases (one launch, tf32 MMA)
    readout_gemm_kernel<<<dim3(8, 20), 256>>>(Wr, Ur, Vr, p_r);
    maxout_kernel<<<64, 256>>>();

    // vocab projection (tf32, proven R10 loader)
    mma_vocab_kernel<<<(Vd + 127)/128, 256>>>(Wy, by, out);
}